// round 9
// baseline (speedup 1.0000x reference)
#include <cuda_runtime.h>
#include <cuda_bf16.h>
#include <cstdint>

// Problem constants: B=64, T=12, P=128, F=128, H=12, MAXC=48
#define Bdim   64
#define Tdim   12
#define Pdim   128
#define Fdim   128
#define Hdim   12
#define MAXC   48
#define Ddim   (Tdim * Fdim)        // 1536 (K)
#define NCdim  (MAXC * Hdim)        // 576  (GEMM N)
#define NNODES 4356

#define TNC  128                    // CTA c-tile (GEMM N per CTA)
#define TK   32                     // K chunk (2 k16 steps)
#define NKC  (Ddim / TK)            // 48
#define NTHREADS 128                // 4 warps, each 64m x 32n

#define ASTR 40                     // bf16 row stride As[m][k]  (32 + 8)  -> 80 B
#define BSTR 136                    // bf16 row stride Bs[k][c]  (128 + 8) -> 272 B

// dynamic smem layout (bytes)
#define ABUF   (64 * ASTR * 2)          // 5120 per buffer
#define BBUF   (TK * BSTR * 2)          // 8704 per buffer
#define OFF_AHI 0
#define OFF_ALO (OFF_AHI + 2 * ABUF)    // 10240
#define OFF_BHI (OFF_ALO + 2 * ABUF)    // 20480
#define OFF_BLO (OFF_BHI + 2 * BBUF)    // 37888
#define SMEM_BYTES (OFF_BLO + 2 * BBUF) // 55296

__device__ __forceinline__ unsigned smem_u32(const void* p) {
    return (unsigned)__cvta_generic_to_shared(p);
}
__device__ __forceinline__ void split2(float x, float y, unsigned& hi, unsigned& lo) {
    __nv_bfloat16 hx = __float2bfloat16_rn(x);
    __nv_bfloat16 hy = __float2bfloat16_rn(y);
    __nv_bfloat16 lx = __float2bfloat16_rn(x - __bfloat162float(hx));
    __nv_bfloat16 ly = __float2bfloat16_rn(y - __bfloat162float(hy));
    hi = (unsigned)__bfloat16_as_ushort(hx) | ((unsigned)__bfloat16_as_ushort(hy) << 16);
    lo = (unsigned)__bfloat16_as_ushort(lx) | ((unsigned)__bfloat16_as_ushort(ly) << 16);
}
__device__ __forceinline__ void ldmx4(unsigned* r, unsigned addr) {
    asm volatile("ldmatrix.sync.aligned.m8n8.x4.shared.b16 {%0,%1,%2,%3}, [%4];"
                 : "=r"(r[0]), "=r"(r[1]), "=r"(r[2]), "=r"(r[3]) : "r"(addr));
}
__device__ __forceinline__ void ldmx4t(unsigned* r, unsigned addr) {
    asm volatile("ldmatrix.sync.aligned.m8n8.x4.trans.shared.b16 {%0,%1,%2,%3}, [%4];"
                 : "=r"(r[0]), "=r"(r[1]), "=r"(r[2]), "=r"(r[3]) : "r"(addr));
}
__device__ __forceinline__ void mma_bf16(float* c, const unsigned* a, unsigned b0, unsigned b1) {
    asm volatile(
        "mma.sync.aligned.m16n8k16.row.col.f32.bf16.bf16.f32 "
        "{%0,%1,%2,%3}, {%4,%5,%6,%7}, {%8,%9}, {%0,%1,%2,%3};"
        : "+f"(c[0]), "+f"(c[1]), "+f"(c[2]), "+f"(c[3])
        : "r"(a[0]), "r"(a[1]), "r"(a[2]), "r"(a[3]), "r"(b0), "r"(b1));
}

__global__ __launch_bounds__(NTHREADS, 2)
void patch_readout_bf16x3_wide_kernel(
    const float* __restrict__ x,        // [B, T, P, F]
    const float* __restrict__ W,        // [P, D, 576]
    const float* __restrict__ bias,     // [P, 576]
    const int*   __restrict__ node_map, // [P, MAXC]
    float*       __restrict__ out)      // [NNODES * B, H]
{
    extern __shared__ char smem[];
    const int p = blockIdx.y;
    int C0 = blockIdx.x * TNC;
    if (C0 + TNC > NCdim) C0 = NCdim - TNC;   // last tile overlaps; identical double-writes

    const int tid  = threadIdx.x;
    const int lane = tid & 31;
    const int warp = tid >> 5;
    const int g    = lane >> 2;
    const int t    = lane & 3;
    const int n_base = warp * 32;       // warp covers cols [n_base, n_base+32)

    const unsigned sb = smem_u32(smem);

    const float* Wp = W + (long long)p * Ddim * NCdim;

    // ---- fill roles ----
    const int a_m  = tid >> 1;          // 0..63 batch row (A side = x)
    const int a_kq = (tid & 1) * 16;    // 16 k-values per thread
    const int b_d  = tid >> 2;          // 0..31 W row within chunk
    const int b_cq = (tid & 3) * 32;    // 32 c-values per thread
    const long long a_row_off = (long long)a_m * (Tdim * Pdim * Fdim);

    // ---- ldmatrix per-lane address terms (byte offsets) ----
    const int q  = lane >> 3;
    const int j7 = lane & 7;
    // A tiles (m16k16, non-trans): q0=(m0-7,k0-7) q1=(m8-15,k0-7) q2=(m0-7,k8-15) q3=(m8-15,k8-15)
    int aTerm[4];
    {
        const int rq = (q & 1) * 8 + j7;
        const int cq = (q >> 1) * 8;
        #pragma unroll
        for (int mi = 0; mi < 4; mi++)
            aTerm[mi] = ((mi * 16 + rq) * ASTR + cq) * 2;
    }
    // B chunks (k16n16, trans): regs 0,1 -> first n8; 2,3 -> second n8
    int bTerm[2];
    {
        const int rk = (q & 1) * 8 + j7;
        #pragma unroll
        for (int nj = 0; nj < 2; nj++)
            bTerm[nj] = (rk * BSTR + n_base + nj * 16 + (q >> 1) * 8) * 2;
    }

    float acc[4][4][4];                 // [m16 tile][n8 tile][frag]
    #pragma unroll
    for (int mi = 0; mi < 4; mi++)
        #pragma unroll
        for (int nj = 0; nj < 4; nj++)
            #pragma unroll
            for (int e = 0; e < 4; e++) acc[mi][nj][e] = 0.0f;

    float4 av[4], bv[8];

    auto load_chunk = [&](int kc) {
        const int K0 = kc * TK;
        const int t0 = K0 >> 7, f0 = K0 & 127;
        const float* ar = x + a_row_off + ((long long)t0 * Pdim + p) * Fdim + f0 + a_kq;
        #pragma unroll
        for (int j = 0; j < 4; j++)
            av[j] = *reinterpret_cast<const float4*>(ar + 4 * j);
        const float* br = Wp + (long long)(K0 + b_d) * NCdim + C0 + b_cq;
        #pragma unroll
        for (int j = 0; j < 8; j++)
            bv[j] = *reinterpret_cast<const float4*>(br + 4 * j);
    };

    auto store_chunk = [&](int buf) {
        // A: x[m][k] -> As[m][k], row stride ASTR
        {
            unsigned h[8], l[8];
            #pragma unroll
            for (int j = 0; j < 4; j++) {
                split2(av[j].x, av[j].y, h[2 * j], l[2 * j]);
                split2(av[j].z, av[j].w, h[2 * j + 1], l[2 * j + 1]);
            }
            char* aH = smem + OFF_AHI + buf * ABUF + a_m * (ASTR * 2) + a_kq * 2;
            char* aL = smem + OFF_ALO + buf * ABUF + a_m * (ASTR * 2) + a_kq * 2;
            *reinterpret_cast<uint4*>(aH)      = make_uint4(h[0], h[1], h[2], h[3]);
            *reinterpret_cast<uint4*>(aH + 16) = make_uint4(h[4], h[5], h[6], h[7]);
            *reinterpret_cast<uint4*>(aL)      = make_uint4(l[0], l[1], l[2], l[3]);
            *reinterpret_cast<uint4*>(aL + 16) = make_uint4(l[4], l[5], l[6], l[7]);
        }
        // B: W[d][c] -> Bs[d][c], row stride BSTR
        {
            unsigned h[16], l[16];
            #pragma unroll
            for (int j = 0; j < 8; j++) {
                split2(bv[j].x, bv[j].y, h[2 * j], l[2 * j]);
                split2(bv[j].z, bv[j].w, h[2 * j + 1], l[2 * j + 1]);
            }
            char* bH = smem + OFF_BHI + buf * BBUF + b_d * (BSTR * 2) + b_cq * 2;
            char* bL = smem + OFF_BLO + buf * BBUF + b_d * (BSTR * 2) + b_cq * 2;
            #pragma unroll
            for (int j = 0; j < 4; j++) {
                *reinterpret_cast<uint4*>(bH + 16 * j) =
                    make_uint4(h[4 * j], h[4 * j + 1], h[4 * j + 2], h[4 * j + 3]);
                *reinterpret_cast<uint4*>(bL + 16 * j) =
                    make_uint4(l[4 * j], l[4 * j + 1], l[4 * j + 2], l[4 * j + 3]);
            }
        }
    };

    load_chunk(0);
    store_chunk(0);
    __syncthreads();

    for (int kc = 0; kc < NKC; kc++) {
        const int buf = kc & 1;
        const bool more = (kc + 1 < NKC);
        if (more) load_chunk(kc + 1);

        #pragma unroll
        for (int s = 0; s < 2; s++) {
            const int k0b = s * 16 * 2;            // byte offset of k16 step
            unsigned aH[4][4], aL[4][4], bH[2][4], bL[2][4];
            const unsigned aHiBase = sb + OFF_AHI + buf * ABUF + k0b;
            const unsigned aLoBase = sb + OFF_ALO + buf * ABUF + k0b;
            #pragma unroll
            for (int mi = 0; mi < 4; mi++) {
                ldmx4(aH[mi], aHiBase + aTerm[mi]);
                ldmx4(aL[mi], aLoBase + aTerm[mi]);
            }
            const unsigned bHiBase = sb + OFF_BHI + buf * BBUF + s * 16 * BSTR * 2;
            const unsigned bLoBase = sb + OFF_BLO + buf * BBUF + s * 16 * BSTR * 2;
            #pragma unroll
            for (int nj = 0; nj < 2; nj++) {
                ldmx4t(bH[nj], bHiBase + bTerm[nj]);
                ldmx4t(bL[nj], bLoBase + bTerm[nj]);
            }
            #pragma unroll
            for (int mi = 0; mi < 4; mi++)
                #pragma unroll
                for (int nj = 0; nj < 4; nj++) {
                    const unsigned* bh = &bH[nj >> 1][(nj & 1) * 2];
                    const unsigned* bl = &bL[nj >> 1][(nj & 1) * 2];
                    mma_bf16(acc[mi][nj], aH[mi], bh[0], bh[1]);
                    mma_bf16(acc[mi][nj], aH[mi], bl[0], bl[1]);
                    mma_bf16(acc[mi][nj], aL[mi], bh[0], bh[1]);
                }
        }

        if (more) {
            store_chunk(buf ^ 1);
            __syncthreads();
        }
    }

    // ---- epilogue: bias + permutation scatter ----
    // C frag: c0=(g,2t) c1=(g,2t+1) c2=(g+8,2t) c3=(g+8,2t+1)
    const int*   nm = node_map + p * MAXC;
    const float* bp = bias + p * NCdim;

    #pragma unroll
    for (int nj = 0; nj < 4; nj++) {
        const int cbase = C0 + n_base + nj * 8 + 2 * t;
        #pragma unroll
        for (int e = 0; e < 2; e++) {
            const int c = cbase + e;
            const int n = c / Hdim;
            const int h = c - n * Hdim;
            const int node = nm[n];
            if (node < NNODES) {
                const float bb = bp[c];
                float* op = out + (long long)node * (Bdim * Hdim) + h;
                #pragma unroll
                for (int mi = 0; mi < 4; mi++) {
                    const int r0 = mi * 16 + g;
                    op[(r0    ) * Hdim] = acc[mi][nj][e]     + bb;
                    op[(r0 + 8) * Hdim] = acc[mi][nj][2 + e] + bb;
                }
            }
        }
    }
}

extern "C" void kernel_launch(void* const* d_in, const int* in_sizes, int n_in,
                              void* d_out, int out_size)
{
    const float* x        = (const float*)d_in[0];
    const float* W        = (const float*)d_in[1];
    const float* bias     = (const float*)d_in[2];
    const int*   node_map = (const int*)d_in[3];
    float*       out      = (float*)d_out;

    cudaFuncSetAttribute(patch_readout_bf16x3_wide_kernel,
                         cudaFuncAttributeMaxDynamicSharedMemorySize, SMEM_BYTES);
    dim3 grid(5, Pdim);     // 5 c-tiles (last overlaps) x 128 patches
    dim3 block(NTHREADS);
    patch_readout_bf16x3_wide_kernel<<<grid, block, SMEM_BYTES>>>(x, W, bias, node_map, out);
}

// round 10
// speedup vs baseline: 1.3670x; 1.3670x over previous
#include <cuda_runtime.h>
#include <cuda_bf16.h>
#include <cstdint>

// Problem constants: B=64, T=12, P=128, F=128, H=12, MAXC=48
#define Bdim   64
#define Tdim   12
#define Pdim   128
#define Fdim   128
#define Hdim   12
#define MAXC   48
#define Ddim   (Tdim * Fdim)        // 1536 (K)
#define NCdim  (MAXC * Hdim)        // 576  (GEMM N)
#define NNODES 4356

#define TNC  128                    // CTA c-tile
#define TK   32                     // K chunk (2 k16 steps)
#define NKC  (Ddim / TK)            // 48
#define NTHREADS 256                // 8 warps: 2(M) x 4(N), each 32m x 32n

#define ASTR 40                     // bf16 row stride As[m][k]  (32 + 8)  -> 80 B
#define BSTR 136                    // bf16 row stride Bs[k][c]  (128 + 8) -> 272 B

// dynamic smem layout (bytes)
#define ABUF   (64 * ASTR * 2)          // 5120 per buffer
#define BBUF   (TK * BSTR * 2)          // 8704 per buffer
#define OFF_AHI 0
#define OFF_ALO (OFF_AHI + 2 * ABUF)    // 10240
#define OFF_BHI (OFF_ALO + 2 * ABUF)    // 20480
#define OFF_BLO (OFF_BHI + 2 * BBUF)    // 37888
#define SMEM_BYTES (OFF_BLO + 2 * BBUF) // 55296

__device__ __forceinline__ unsigned smem_u32(const void* p) {
    return (unsigned)__cvta_generic_to_shared(p);
}
__device__ __forceinline__ void split2(float x, float y, unsigned& hi, unsigned& lo) {
    __nv_bfloat16 hx = __float2bfloat16_rn(x);
    __nv_bfloat16 hy = __float2bfloat16_rn(y);
    __nv_bfloat16 lx = __float2bfloat16_rn(x - __bfloat162float(hx));
    __nv_bfloat16 ly = __float2bfloat16_rn(y - __bfloat162float(hy));
    hi = (unsigned)__bfloat16_as_ushort(hx) | ((unsigned)__bfloat16_as_ushort(hy) << 16);
    lo = (unsigned)__bfloat16_as_ushort(lx) | ((unsigned)__bfloat16_as_ushort(ly) << 16);
}
__device__ __forceinline__ void ldmx4(unsigned* r, unsigned addr) {
    asm volatile("ldmatrix.sync.aligned.m8n8.x4.shared.b16 {%0,%1,%2,%3}, [%4];"
                 : "=r"(r[0]), "=r"(r[1]), "=r"(r[2]), "=r"(r[3]) : "r"(addr));
}
__device__ __forceinline__ void ldmx4t(unsigned* r, unsigned addr) {
    asm volatile("ldmatrix.sync.aligned.m8n8.x4.trans.shared.b16 {%0,%1,%2,%3}, [%4];"
                 : "=r"(r[0]), "=r"(r[1]), "=r"(r[2]), "=r"(r[3]) : "r"(addr));
}
__device__ __forceinline__ void mma_bf16(float* c, const unsigned* a, unsigned b0, unsigned b1) {
    asm volatile(
        "mma.sync.aligned.m16n8k16.row.col.f32.bf16.bf16.f32 "
        "{%0,%1,%2,%3}, {%4,%5,%6,%7}, {%8,%9}, {%0,%1,%2,%3};"
        : "+f"(c[0]), "+f"(c[1]), "+f"(c[2]), "+f"(c[3])
        : "r"(a[0]), "r"(a[1]), "r"(a[2]), "r"(a[3]), "r"(b0), "r"(b1));
}

__global__ __launch_bounds__(NTHREADS, 2)
void patch_readout_bf16x3_mid_kernel(
    const float* __restrict__ x,        // [B, T, P, F]
    const float* __restrict__ W,        // [P, D, 576]
    const float* __restrict__ bias,     // [P, 576]
    const int*   __restrict__ node_map, // [P, MAXC]
    float*       __restrict__ out)      // [NNODES * B, H]
{
    extern __shared__ char smem[];
    const int p = blockIdx.y;
    int C0 = blockIdx.x * TNC;
    if (C0 + TNC > NCdim) C0 = NCdim - TNC;   // last tile overlaps; identical double-writes

    const int tid  = threadIdx.x;
    const int lane = tid & 31;
    const int warp = tid >> 5;
    const int g    = lane >> 2;
    const int t    = lane & 3;
    const int m_base = (warp >> 2) * 32;   // 2 M-groups of 32 batch rows
    const int n_base = (warp & 3) * 32;    // 4 N-groups of 32 cols

    const unsigned sb = smem_u32(smem);
    const float* Wp = W + (long long)p * Ddim * NCdim;

    // ---- fill roles ----
    const int a_m  = tid >> 2;          // 0..63 batch row
    const int a_kq = (tid & 3) * 8;     // 8 k-values per thread
    const int b_d  = tid >> 3;          // 0..31 W row within chunk
    const int b_cq = (tid & 7) * 16;    // 16 c-values per thread
    const long long a_row_off = (long long)a_m * (Tdim * Pdim * Fdim);

    // ---- ldmatrix per-lane address terms (byte offsets) ----
    const int q  = lane >> 3;
    const int j7 = lane & 7;
    // A tiles (m16k16, non-trans): q0=(m0-7,k0-7) q1=(m8-15,k0-7) q2=(m0-7,k8-15) q3=(m8-15,k8-15)
    int aTerm[2];
    {
        const int rq = (q & 1) * 8 + j7;
        const int cq = (q >> 1) * 8;
        #pragma unroll
        for (int mi = 0; mi < 2; mi++)
            aTerm[mi] = ((m_base + mi * 16 + rq) * ASTR + cq) * 2;
    }
    // B tiles (k16n16, trans): regs 0,1 -> first n8; 2,3 -> second n8
    int bTerm[2];
    {
        const int rk = (q & 1) * 8 + j7;
        #pragma unroll
        for (int nj = 0; nj < 2; nj++)
            bTerm[nj] = (rk * BSTR + n_base + nj * 16 + (q >> 1) * 8) * 2;
    }

    float acc[2][4][4];                 // [m16 tile][n8 tile][frag]
    #pragma unroll
    for (int mi = 0; mi < 2; mi++)
        #pragma unroll
        for (int nj = 0; nj < 4; nj++)
            #pragma unroll
            for (int e = 0; e < 4; e++) acc[mi][nj][e] = 0.0f;

    float4 av[2], bv[4];

    auto load_chunk = [&](int kc) {
        const int K0 = kc * TK;
        const int t0 = K0 >> 7, f0 = K0 & 127;
        const float* ar = x + a_row_off + ((long long)t0 * Pdim + p) * Fdim + f0 + a_kq;
        av[0] = *reinterpret_cast<const float4*>(ar);
        av[1] = *reinterpret_cast<const float4*>(ar + 4);
        const float* br = Wp + (long long)(K0 + b_d) * NCdim + C0 + b_cq;
        #pragma unroll
        for (int j = 0; j < 4; j++)
            bv[j] = *reinterpret_cast<const float4*>(br + 4 * j);
    };

    auto store_chunk = [&](int buf) {
        // A: x[m][k] -> As[m][k]
        {
            unsigned h[4], l[4];
            split2(av[0].x, av[0].y, h[0], l[0]);
            split2(av[0].z, av[0].w, h[1], l[1]);
            split2(av[1].x, av[1].y, h[2], l[2]);
            split2(av[1].z, av[1].w, h[3], l[3]);
            char* aH = smem + OFF_AHI + buf * ABUF + a_m * (ASTR * 2) + a_kq * 2;
            char* aL = smem + OFF_ALO + buf * ABUF + a_m * (ASTR * 2) + a_kq * 2;
            *reinterpret_cast<uint4*>(aH) = make_uint4(h[0], h[1], h[2], h[3]);
            *reinterpret_cast<uint4*>(aL) = make_uint4(l[0], l[1], l[2], l[3]);
        }
        // B: W[d][c] -> Bs[d][c]
        {
            unsigned h[8], l[8];
            #pragma unroll
            for (int j = 0; j < 4; j++) {
                split2(bv[j].x, bv[j].y, h[2 * j], l[2 * j]);
                split2(bv[j].z, bv[j].w, h[2 * j + 1], l[2 * j + 1]);
            }
            char* bH = smem + OFF_BHI + buf * BBUF + b_d * (BSTR * 2) + b_cq * 2;
            char* bL = smem + OFF_BLO + buf * BBUF + b_d * (BSTR * 2) + b_cq * 2;
            *reinterpret_cast<uint4*>(bH)      = make_uint4(h[0], h[1], h[2], h[3]);
            *reinterpret_cast<uint4*>(bH + 16) = make_uint4(h[4], h[5], h[6], h[7]);
            *reinterpret_cast<uint4*>(bL)      = make_uint4(l[0], l[1], l[2], l[3]);
            *reinterpret_cast<uint4*>(bL + 16) = make_uint4(l[4], l[5], l[6], l[7]);
        }
    };

    load_chunk(0);
    store_chunk(0);
    __syncthreads();

    for (int kc = 0; kc < NKC; kc++) {
        const int buf = kc & 1;
        const bool more = (kc + 1 < NKC);
        if (more) load_chunk(kc + 1);

        #pragma unroll
        for (int s = 0; s < 2; s++) {
            const int k0b = s * 16 * 2;            // byte offset of k16 step (A side)
            unsigned aH[2][4], aL[2][4], bH[2][4], bL[2][4];
            const unsigned aHiBase = sb + OFF_AHI + buf * ABUF + k0b;
            const unsigned aLoBase = sb + OFF_ALO + buf * ABUF + k0b;
            #pragma unroll
            for (int mi = 0; mi < 2; mi++) {
                ldmx4(aH[mi], aHiBase + aTerm[mi]);
                ldmx4(aL[mi], aLoBase + aTerm[mi]);
            }
            const unsigned bHiBase = sb + OFF_BHI + buf * BBUF + s * 16 * BSTR * 2;
            const unsigned bLoBase = sb + OFF_BLO + buf * BBUF + s * 16 * BSTR * 2;
            #pragma unroll
            for (int nj = 0; nj < 2; nj++) {
                ldmx4t(bH[nj], bHiBase + bTerm[nj]);
                ldmx4t(bL[nj], bLoBase + bTerm[nj]);
            }
            #pragma unroll
            for (int mi = 0; mi < 2; mi++)
                #pragma unroll
                for (int nj = 0; nj < 4; nj++) {
                    const unsigned* bh = &bH[nj >> 1][(nj & 1) * 2];
                    const unsigned* bl = &bL[nj >> 1][(nj & 1) * 2];
                    mma_bf16(acc[mi][nj], aH[mi], bh[0], bh[1]);
                    mma_bf16(acc[mi][nj], aH[mi], bl[0], bl[1]);
                    mma_bf16(acc[mi][nj], aL[mi], bh[0], bh[1]);
                }
        }

        if (more) {
            store_chunk(buf ^ 1);
            __syncthreads();
        }
    }

    // ---- epilogue: bias + permutation scatter ----
    // C frag: c0=(g,2t) c1=(g,2t+1) c2=(g+8,2t) c3=(g+8,2t+1)
    const int*   nm = node_map + p * MAXC;
    const float* bp = bias + p * NCdim;

    #pragma unroll
    for (int nj = 0; nj < 4; nj++) {
        const int cbase = C0 + n_base + nj * 8 + 2 * t;
        #pragma unroll
        for (int e = 0; e < 2; e++) {
            const int c = cbase + e;
            const int n = c / Hdim;
            const int h = c - n * Hdim;
            const int node = nm[n];
            if (node < NNODES) {
                const float bb = bp[c];
                float* op = out + (long long)node * (Bdim * Hdim) + h;
                #pragma unroll
                for (int mi = 0; mi < 2; mi++) {
                    const int r0 = m_base + mi * 16 + g;
                    op[(r0    ) * Hdim] = acc[mi][nj][e]     + bb;
                    op[(r0 + 8) * Hdim] = acc[mi][nj][2 + e] + bb;
                }
            }
        }
    }
}

extern "C" void kernel_launch(void* const* d_in, const int* in_sizes, int n_in,
                              void* d_out, int out_size)
{
    const float* x        = (const float*)d_in[0];
    const float* W        = (const float*)d_in[1];
    const float* bias     = (const float*)d_in[2];
    const int*   node_map = (const int*)d_in[3];
    float*       out      = (float*)d_out;

    cudaFuncSetAttribute(patch_readout_bf16x3_mid_kernel,
                         cudaFuncAttributeMaxDynamicSharedMemorySize, SMEM_BYTES);
    dim3 grid(5, Pdim);     // 5 c-tiles (last overlaps) x 128 patches
    dim3 block(NTHREADS);
    patch_readout_bf16x3_mid_kernel<<<grid, block, SMEM_BYTES>>>(x, W, bias, node_map, out);
}

// round 11
// speedup vs baseline: 1.7120x; 1.2524x over previous
#include <cuda_runtime.h>
#include <cuda_bf16.h>
#include <cstdint>

// Problem constants: B=64, T=12, P=128, F=128, H=12, MAXC=48
#define Bdim   64
#define Tdim   12
#define Pdim   128
#define Fdim   128
#define Hdim   12
#define MAXC   48
#define Ddim   (Tdim * Fdim)        // 1536 (K)
#define NCdim  (MAXC * Hdim)        // 576  (GEMM N)
#define NNODES 4356

#define TN 64
#define TK 32
#define NKC (Ddim / TK)             // 48
#define NTHREADS 256                // 8 warps: 2(M) x 4(N), each 32m x 16n
#define ASTR 40                     // bf16 row stride As[m][k]  (32 + 8)
#define BSTR 72                     // bf16 row stride Bs[k][c]  (64 + 8)

__device__ __forceinline__ unsigned smem_u32(const void* p) {
    return (unsigned)__cvta_generic_to_shared(p);
}

// split two fp32 into packed bf16 hi / lo pairs
__device__ __forceinline__ void split2(float x, float y, unsigned& hi, unsigned& lo) {
    __nv_bfloat16 hx = __float2bfloat16_rn(x);
    __nv_bfloat16 hy = __float2bfloat16_rn(y);
    __nv_bfloat16 lx = __float2bfloat16_rn(x - __bfloat162float(hx));
    __nv_bfloat16 ly = __float2bfloat16_rn(y - __bfloat162float(hy));
    hi = (unsigned)__bfloat16_as_ushort(hx) | ((unsigned)__bfloat16_as_ushort(hy) << 16);
    lo = (unsigned)__bfloat16_as_ushort(lx) | ((unsigned)__bfloat16_as_ushort(ly) << 16);
}

__device__ __forceinline__ void ldmx4(unsigned* r, unsigned addr) {
    asm volatile("ldmatrix.sync.aligned.m8n8.x4.shared.b16 {%0,%1,%2,%3}, [%4];"
                 : "=r"(r[0]), "=r"(r[1]), "=r"(r[2]), "=r"(r[3]) : "r"(addr));
}
__device__ __forceinline__ void ldmx4t(unsigned* r, unsigned addr) {
    asm volatile("ldmatrix.sync.aligned.m8n8.x4.trans.shared.b16 {%0,%1,%2,%3}, [%4];"
                 : "=r"(r[0]), "=r"(r[1]), "=r"(r[2]), "=r"(r[3]) : "r"(addr));
}
__device__ __forceinline__ void mma_bf16(float* c, const unsigned* a, unsigned b0, unsigned b1) {
    asm volatile(
        "mma.sync.aligned.m16n8k16.row.col.f32.bf16.bf16.f32 "
        "{%0,%1,%2,%3}, {%4,%5,%6,%7}, {%8,%9}, {%0,%1,%2,%3};"
        : "+f"(c[0]), "+f"(c[1]), "+f"(c[2]), "+f"(c[3])
        : "r"(a[0]), "r"(a[1]), "r"(a[2]), "r"(a[3]), "r"(b0), "r"(b1));
}

// min 3 CTAs/SM -> ptxas register cap 85 -> 24 warps/SM residency
__global__ __launch_bounds__(NTHREADS, 3)
void patch_readout_bf16x3_occ_kernel(
    const float* __restrict__ x,        // [B, T, P, F]
    const float* __restrict__ W,        // [P, D, 576]
    const float* __restrict__ bias,     // [P, 576]
    const int*   __restrict__ node_map, // [P, MAXC]
    float*       __restrict__ out)      // [NNODES * B, H]
{
    const int p    = blockIdx.y;
    const int C0   = blockIdx.x * TN;
    const int tid  = threadIdx.x;
    const int lane = tid & 31;
    const int warp = tid >> 5;
    const int g    = lane >> 2;
    const int t    = lane & 3;
    const int m_base = (warp >> 2) * 32;   // 2 M-groups of 32 rows
    const int n_base = (warp & 3) * 16;    // 4 N-groups of 16 cols

    __shared__ __align__(16) __nv_bfloat16 AsHi[2][64][ASTR];
    __shared__ __align__(16) __nv_bfloat16 AsLo[2][64][ASTR];
    __shared__ __align__(16) __nv_bfloat16 BsHi[2][TK][BSTR];
    __shared__ __align__(16) __nv_bfloat16 BsLo[2][TK][BSTR];

    const unsigned aHiB = smem_u32(AsHi), aLoB = smem_u32(AsLo);
    const unsigned bHiB = smem_u32(BsHi), bLoB = smem_u32(BsLo);
    const unsigned ABUF = 64 * ASTR * 2;
    const unsigned BBUF = TK * BSTR * 2;

    const float* xp = x + p * Fdim;
    const float* Wp = W + (long long)p * Ddim * NCdim;

    // ---- fill roles ----
    const int a_m  = tid >> 2;          // 0..63 batch row
    const int a_kq = (tid & 3) * 8;     // k octet
    const int b_k  = tid >> 3;          // 0..31 W row within chunk
    const int b_cq = (tid & 7) * 8;     // c octet
    const long long a_row_off = (long long)a_m * (Tdim * Pdim * Fdim);

    // ---- ldmatrix per-lane address terms ----
    const int q  = lane >> 3;
    const int j7 = lane & 7;
    int rowTermA[2];
    {
        const int rq = (q & 1) * 8 + j7;
        const int cq = (q >> 1) * 8;
        rowTermA[0] = (m_base +  0 + rq) * ASTR + cq;
        rowTermA[1] = (m_base + 16 + rq) * ASTR + cq;
    }
    const int rowTermB = ((q & 1) * 8 + j7) * BSTR + n_base + (q >> 1) * 8;

    float acc[2][2][4];
    #pragma unroll
    for (int i = 0; i < 2; i++)
        #pragma unroll
        for (int jj = 0; jj < 2; jj++)
            #pragma unroll
            for (int r = 0; r < 4; r++) acc[i][jj][r] = 0.0f;

    float4 av0, av1, bv0, bv1;

    auto load_chunk = [&](int kc) {
        const int K0 = kc * TK;
        const int tt = K0 >> 7;
        const int f0 = K0 & 127;
        const float* ap = xp + a_row_off + tt * (Pdim * Fdim) + f0 + a_kq;
        av0 = *reinterpret_cast<const float4*>(ap);
        av1 = *reinterpret_cast<const float4*>(ap + 4);
        const float* bp = Wp + (long long)(K0 + b_k) * NCdim + C0 + b_cq;
        bv0 = *reinterpret_cast<const float4*>(bp);
        bv1 = *reinterpret_cast<const float4*>(bp + 4);
    };
    auto store_chunk = [&](int buf) {
        unsigned h0, l0, h1, l1, h2, l2, h3, l3;
        split2(av0.x, av0.y, h0, l0); split2(av0.z, av0.w, h1, l1);
        split2(av1.x, av1.y, h2, l2); split2(av1.z, av1.w, h3, l3);
        *reinterpret_cast<uint4*>(&AsHi[buf][a_m][a_kq]) = make_uint4(h0, h1, h2, h3);
        *reinterpret_cast<uint4*>(&AsLo[buf][a_m][a_kq]) = make_uint4(l0, l1, l2, l3);
        split2(bv0.x, bv0.y, h0, l0); split2(bv0.z, bv0.w, h1, l1);
        split2(bv1.x, bv1.y, h2, l2); split2(bv1.z, bv1.w, h3, l3);
        *reinterpret_cast<uint4*>(&BsHi[buf][b_k][b_cq]) = make_uint4(h0, h1, h2, h3);
        *reinterpret_cast<uint4*>(&BsLo[buf][b_k][b_cq]) = make_uint4(l0, l1, l2, l3);
    };

    load_chunk(0);
    store_chunk(0);
    __syncthreads();

    for (int kc = 0; kc < NKC; kc++) {
        const int buf = kc & 1;
        const bool more = (kc + 1 < NKC);
        if (more) load_chunk(kc + 1);

        #pragma unroll
        for (int s = 0; s < 2; s++) {
            const int k0 = s * 16;
            unsigned aH[2][4], aL[2][4], bH[4], bL[4];
            #pragma unroll
            for (int i = 0; i < 2; i++) {
                const unsigned ao = buf * ABUF + (unsigned)(rowTermA[i] + k0) * 2u;
                ldmx4(aH[i], aHiB + ao);
                ldmx4(aL[i], aLoB + ao);
            }
            {
                const unsigned bo = buf * BBUF + (unsigned)(rowTermB + k0 * BSTR) * 2u;
                ldmx4t(bH, bHiB + bo);
                ldmx4t(bL, bLoB + bo);
            }
            #pragma unroll
            for (int i = 0; i < 2; i++)
                #pragma unroll
                for (int jj = 0; jj < 2; jj++) {
                    mma_bf16(acc[i][jj], aH[i], bH[2 * jj], bH[2 * jj + 1]);
                    mma_bf16(acc[i][jj], aH[i], bL[2 * jj], bL[2 * jj + 1]);
                    mma_bf16(acc[i][jj], aL[i], bH[2 * jj], bH[2 * jj + 1]);
                }
        }

        if (more) {
            store_chunk(buf ^ 1);
            __syncthreads();
        }
    }

    // ---- epilogue: bias + permutation scatter ----
    // C frag: c0=(g,2t) c1=(g,2t+1) c2=(g+8,2t) c3=(g+8,2t+1)
    const int*   nm = node_map + p * MAXC;
    const float* bp = bias + p * NCdim;

    #pragma unroll
    for (int i = 0; i < 2; i++) {
        const int r0 = m_base + i * 16 + g;
        const int r1 = r0 + 8;
        #pragma unroll
        for (int jj = 0; jj < 2; jj++) {
            const int cbase = C0 + n_base + jj * 8 + 2 * t;
            #pragma unroll
            for (int e = 0; e < 2; e++) {
                const int c = cbase + e;
                const int n = c / Hdim;
                const int h = c - n * Hdim;
                const int node = nm[n];
                if (node < NNODES) {
                    const float bb = bp[c];
                    out[(node * Bdim + r0) * Hdim + h] = acc[i][jj][e]     + bb;
                    out[(node * Bdim + r1) * Hdim + h] = acc[i][jj][2 + e] + bb;
                }
            }
        }
    }
}

extern "C" void kernel_launch(void* const* d_in, const int* in_sizes, int n_in,
                              void* d_out, int out_size)
{
    const float* x        = (const float*)d_in[0];
    const float* W        = (const float*)d_in[1];
    const float* bias     = (const float*)d_in[2];
    const int*   node_map = (const int*)d_in[3];
    float*       out      = (float*)d_out;

    dim3 grid(NCdim / TN, Pdim);   // (9, 128)
    dim3 block(NTHREADS);
    patch_readout_bf16x3_occ_kernel<<<grid, block>>>(x, W, bias, node_map, out);
}